// round 3
// baseline (speedup 1.0000x reference)
#include <cuda_runtime.h>
#include <cstdint>

// Problem constants
#define B 128
#define T 512
#define I 50
#define H 256

// recurrence split-K config (512 threads: thread = (neuron n, k-half kh))
#define KH        128        // k per half
#define K_SM_H    32         // k per half kept in shared memory
#define K_RG_H    96         // k per half kept in registers (48 ulonglong)
#define WPITCH    36         // smem pitch (floats) for 32-float W chunks: 36 mod 32 = 4 -> conflict-free LDS.128

// Scratch: xp[dir][t][b][h]  (fp32), 2*512*128*256 floats = 134 MB
__device__ float g_xp[2u * T * B * H];

// ---------------------------------------------------------------------------
// packed fp32x2 helpers (Blackwell)
// ---------------------------------------------------------------------------
__device__ __forceinline__ unsigned long long ffma2(unsigned long long a,
                                                    unsigned long long b,
                                                    unsigned long long c) {
    unsigned long long d;
    asm("fma.rn.f32x2 %0, %1, %2, %3;" : "=l"(d) : "l"(a), "l"(b), "l"(c));
    return d;
}
__device__ __forceinline__ float2 u2f(unsigned long long v) {
    float2 f;
    asm("mov.b64 {%0, %1}, %2;" : "=f"(f.x), "=f"(f.y) : "l"(v));
    return f;
}
__device__ __forceinline__ unsigned long long f2u(float lo, float hi) {
    unsigned long long v;
    asm("mov.b64 %0, {%1, %2};" : "=l"(v) : "f"(lo), "f"(hi));
    return v;
}

// ---------------------------------------------------------------------------
// Kernel 1: input projection. xp[d][t][b][h] = x[b][t_src] . w_ih_d[h] + biases
// x staged padded to 52 floats/row -> 13 broadcast LDS.128 per batch row.
// ---------------------------------------------------------------------------
#define IPAD 52
__global__ __launch_bounds__(256) void proj_kernel(
    const float* __restrict__ x,
    const float* __restrict__ w_ih_f, const float* __restrict__ b_ih_f, const float* __restrict__ b_hh_f,
    const float* __restrict__ w_ih_b, const float* __restrict__ b_ih_b, const float* __restrict__ b_hh_b)
{
    __shared__ float xs[B * IPAD];   // 26.6 KB, padded

    const int t   = blockIdx.x;
    const int dir = blockIdx.y;
    const int h   = threadIdx.x;
    const int t_src = dir ? (T - 1 - t) : t;

    // zero padding lanes
    for (int idx = threadIdx.x; idx < B * IPAD; idx += blockDim.x) xs[idx] = 0.f;
    __syncthreads();
    for (int idx = threadIdx.x; idx < B * I; idx += blockDim.x) {
        int b = idx / I;
        int i = idx - b * I;
        xs[b * IPAD + i] = x[((size_t)b * T + t_src) * I + i];
    }

    const float* w = dir ? w_ih_b : w_ih_f;
    // 26 packed weight pairs (last pair zero-padded)
    unsigned long long wr[26];
    {
        const float* wp = w + (size_t)h * I;
        #pragma unroll
        for (int i = 0; i < 25; i++) wr[i] = f2u(wp[2 * i], wp[2 * i + 1]);
        wr[25] = 0ull;
    }
    const float bias = dir ? (b_ih_b[h] + b_hh_b[h]) : (b_ih_f[h] + b_hh_f[h]);

    __syncthreads();

    float* xp_out = g_xp + (((size_t)dir * T + t) * B) * H + h;
    #pragma unroll 2
    for (int b = 0; b < B; b++) {
        const ulonglong2* xb = reinterpret_cast<const ulonglong2*>(&xs[b * IPAD]);
        unsigned long long a0 = 0ull, a1 = 0ull;
        #pragma unroll
        for (int i = 0; i < 13; i++) {
            ulonglong2 xv = xb[i];
            a0 = ffma2(xv.x, wr[2 * i], a0);
            a1 = ffma2(xv.y, wr[2 * i + 1], a1);
        }
        float2 f0 = u2f(a0), f1 = u2f(a1);
        xp_out[(size_t)b * H] = bias + ((f0.x + f0.y) + (f1.x + f1.y));
    }
}

// ---------------------------------------------------------------------------
// Kernel 2: recurrence, split-K. 128 CTAs x 512 threads.
// blockIdx/64 = direction, 2 batch rows per CTA.
// Thread t: neuron n = t&255, k-half kh = t>>8 (k in [kh*128, kh*128+128)).
// W[n, kh-half]: first 32 k from SMEM (pitch 36), last 96 k in registers.
// half-1 deposits partials in psum; half-0 combines (+xp, relu), writes h & out.
// h double-buffered in SMEM. 2 barriers per step.
// ---------------------------------------------------------------------------
__global__ __launch_bounds__(512, 1) void rnn_kernel(
    const float* __restrict__ w_hh_f,
    const float* __restrict__ w_hh_b,
    float* __restrict__ out)
{
    extern __shared__ float sm[];
    float* Wsh  = sm;                     // [2*256][WPITCH] = 18432 floats (73,728 B)
    float* hs   = sm + 2 * 256 * WPITCH;  // [2 buf][2 rows][256] = 1024 floats
    float* psum = hs + 1024;              // [2 rows][256] = 512 floats

    const int dir = blockIdx.x >> 6;
    const int jb  = blockIdx.x & 63;
    const int b0  = 2 * jb;
    const int t   = threadIdx.x;
    const int n   = t & 255;
    const int kh  = t >> 8;               // warp-uniform
    const int kbase = kh * KH;

    const float* __restrict__ W = dir ? w_hh_b : w_hh_f;

    // stage W[:, kh*128 : kh*128+32] for both halves into Wsh
    for (int idx = t; idx < 2 * 256 * K_SM_H; idx += 512) {
        int half = idx >> 13;              // / (256*32)
        int rem  = idx & 8191;
        int nn   = rem >> 5;
        int kk   = rem & 31;
        Wsh[(half * 256 + nn) * WPITCH + kk] = W[nn * H + half * KH + kk];
    }
    // W[n, kbase+32 : kbase+128] -> 24 ulonglong2 (96 regs)
    ulonglong2 wreg[24];
    {
        const ulonglong2* wrow = reinterpret_cast<const ulonglong2*>(W + (size_t)n * H + kbase + K_SM_H);
        #pragma unroll
        for (int r = 0; r < 24; r++) wreg[r] = wrow[r];
    }
    // h0 = 0 (buf 0 = first 512 floats of hs)
    hs[t] = 0.f;
    __syncthreads();

    // xp / out pointers (used by half 0 only)
    const float* xp0 = g_xp + ((size_t)dir * T * B + b0) * H + n;
    const float* xp1 = xp0 + H;
    const size_t step_stride = (size_t)B * H;
    float xa = 0.f, xb = 0.f;
    if (kh == 0) { xa = __ldg(xp0); xb = __ldg(xp1); }
    float* out_t = out + (size_t)dir * H + n;

    const ulonglong2* wv = reinterpret_cast<const ulonglong2*>(Wsh + (kh * 256 + n) * WPITCH);

    int buf = 0;
    for (int s = 0; s < T; s++) {
        float nxa = 0.f, nxb = 0.f;
        if (kh == 0 && s < T - 1) {
            nxa = __ldg(xp0 + (size_t)(s + 1) * step_stride);
            nxb = __ldg(xp1 + (size_t)(s + 1) * step_stride);
        }

        const ulonglong2* hv0 = reinterpret_cast<const ulonglong2*>(hs + buf * 512 + kbase);
        const ulonglong2* hv1 = reinterpret_cast<const ulonglong2*>(hs + buf * 512 + 256 + kbase);

        unsigned long long aA0 = 0ull, aB0 = 0ull, aA1 = 0ull, aB1 = 0ull;

        // k in [kbase, kbase+32): W from shared
        #pragma unroll
        for (int i = 0; i < K_SM_H / 4; i++) {
            ulonglong2 w  = wv[i];
            ulonglong2 ha = hv0[i];
            ulonglong2 hb = hv1[i];
            aA0 = ffma2(w.x, ha.x, aA0);
            aB0 = ffma2(w.y, ha.y, aB0);
            aA1 = ffma2(w.x, hb.x, aA1);
            aB1 = ffma2(w.y, hb.y, aB1);
        }
        // k in [kbase+32, kbase+128): W from regs
        #pragma unroll
        for (int r = 0; r < 24; r++) {
            ulonglong2 w  = wreg[r];
            ulonglong2 ha = hv0[K_SM_H / 4 + r];
            ulonglong2 hb = hv1[K_SM_H / 4 + r];
            aA0 = ffma2(w.x, ha.x, aA0);
            aB0 = ffma2(w.y, ha.y, aB0);
            aA1 = ffma2(w.x, hb.x, aA1);
            aB1 = ffma2(w.y, hb.y, aB1);
        }

        float2 fA0 = u2f(aA0), fB0 = u2f(aB0);
        float2 fA1 = u2f(aA1), fB1 = u2f(aB1);
        float s0 = (fA0.x + fA0.y) + (fB0.x + fB0.y);
        float s1 = (fA1.x + fA1.y) + (fB1.x + fB1.y);

        if (kh == 1) {
            psum[n]       = s0;
            psum[256 + n] = s1;
        }
        __syncthreads();

        const int nb = buf ^ 1;
        if (kh == 0) {
            float h0 = fmaxf(xa + s0 + psum[n], 0.f);
            float h1 = fmaxf(xb + s1 + psum[256 + n], 0.f);

            const int time = dir ? (T - 1 - s) : s;
            out_t[((size_t)b0 * T + time) * (2 * H)] = h0;
            out_t[((size_t)(b0 + 1) * T + time) * (2 * H)] = h1;

            hs[nb * 512 + n]       = h0;
            hs[nb * 512 + 256 + n] = h1;
            xa = nxa;
            xb = nxb;
        }
        __syncthreads();
        buf = nb;
    }
}

// ---------------------------------------------------------------------------
extern "C" void kernel_launch(void* const* d_in, const int* in_sizes, int n_in,
                              void* d_out, int out_size)
{
    const float* x      = (const float*)d_in[0];
    const float* w_ih_f = (const float*)d_in[1];
    const float* w_hh_f = (const float*)d_in[2];
    const float* b_ih_f = (const float*)d_in[3];
    const float* b_hh_f = (const float*)d_in[4];
    const float* w_ih_b = (const float*)d_in[5];
    const float* w_hh_b = (const float*)d_in[6];
    const float* b_ih_b = (const float*)d_in[7];
    const float* b_hh_b = (const float*)d_in[8];
    float* out = (float*)d_out;

    const int smem_bytes = (2 * 256 * WPITCH + 1024 + 512) * 4;  // 79,872 B
    static bool attr_set = false;
    if (!attr_set) {
        cudaFuncSetAttribute(rnn_kernel, cudaFuncAttributeMaxDynamicSharedMemorySize, smem_bytes);
        attr_set = true;
    }

    proj_kernel<<<dim3(T, 2), 256>>>(x, w_ih_f, b_ih_f, b_hh_f, w_ih_b, b_ih_b, b_hh_b);
    rnn_kernel<<<128, 512, smem_bytes>>>(w_hh_f, w_hh_b, out);
}

// round 4
// speedup vs baseline: 1.1050x; 1.1050x over previous
#include <cuda_runtime.h>
#include <cstdint>

// Problem constants
#define B 128
#define T 512
#define I 50
#define H 256

// recurrence config: 512 threads, thread t -> (neuron n = t>>1, k-half kh = t&1)
#define K_SM_H  40          // k per half from shared memory (10 LDS.128)
#define K_RG_H  88          // k per half in registers (22 ulonglong2 = 88 regs)
#define WPITCH  44          // smem pitch (floats); 44*t banks give conflict-free LDS.128
#define HROW    264         // padded h row: h[k] stored at k + 4*(k>=128)  (260 used, pad to 264)

// Scratch: xp[dir][t][b][h]  (fp32), 134 MB
__device__ float g_xp[2u * T * B * H];

// ---------------------------------------------------------------------------
// packed fp32x2 helpers (Blackwell)
// ---------------------------------------------------------------------------
__device__ __forceinline__ unsigned long long ffma2(unsigned long long a,
                                                    unsigned long long b,
                                                    unsigned long long c) {
    unsigned long long d;
    asm("fma.rn.f32x2 %0, %1, %2, %3;" : "=l"(d) : "l"(a), "l"(b), "l"(c));
    return d;
}
__device__ __forceinline__ float2 u2f(unsigned long long v) {
    float2 f;
    asm("mov.b64 {%0, %1}, %2;" : "=f"(f.x), "=f"(f.y) : "l"(v));
    return f;
}
__device__ __forceinline__ unsigned long long f2u(float lo, float hi) {
    unsigned long long v;
    asm("mov.b64 %0, {%1, %2};" : "=l"(v) : "f"(lo), "f"(hi));
    return v;
}

// ---------------------------------------------------------------------------
// Kernel 1: input projection (unchanged from round 2/3 — ~115 us, not the bottleneck)
// ---------------------------------------------------------------------------
#define IPAD 52
__global__ __launch_bounds__(256) void proj_kernel(
    const float* __restrict__ x,
    const float* __restrict__ w_ih_f, const float* __restrict__ b_ih_f, const float* __restrict__ b_hh_f,
    const float* __restrict__ w_ih_b, const float* __restrict__ b_ih_b, const float* __restrict__ b_hh_b)
{
    __shared__ float xs[B * IPAD];

    const int t   = blockIdx.x;
    const int dir = blockIdx.y;
    const int h   = threadIdx.x;
    const int t_src = dir ? (T - 1 - t) : t;

    for (int idx = threadIdx.x; idx < B * IPAD; idx += blockDim.x) xs[idx] = 0.f;
    __syncthreads();
    for (int idx = threadIdx.x; idx < B * I; idx += blockDim.x) {
        int b = idx / I;
        int i = idx - b * I;
        xs[b * IPAD + i] = x[((size_t)b * T + t_src) * I + i];
    }

    const float* w = dir ? w_ih_b : w_ih_f;
    unsigned long long wr[26];
    {
        const float* wp = w + (size_t)h * I;
        #pragma unroll
        for (int i = 0; i < 25; i++) wr[i] = f2u(wp[2 * i], wp[2 * i + 1]);
        wr[25] = 0ull;
    }
    const float bias = dir ? (b_ih_b[h] + b_hh_b[h]) : (b_ih_f[h] + b_hh_f[h]);

    __syncthreads();

    float* xp_out = g_xp + (((size_t)dir * T + t) * B) * H + h;
    #pragma unroll 2
    for (int b = 0; b < B; b++) {
        const ulonglong2* xb = reinterpret_cast<const ulonglong2*>(&xs[b * IPAD]);
        unsigned long long a0 = 0ull, a1 = 0ull;
        #pragma unroll
        for (int i = 0; i < 13; i++) {
            ulonglong2 xv = xb[i];
            a0 = ffma2(xv.x, wr[2 * i], a0);
            a1 = ffma2(xv.y, wr[2 * i + 1], a1);
        }
        float2 f0 = u2f(a0), f1 = u2f(a1);
        xp_out[(size_t)b * H] = bias + ((f0.x + f0.y) + (f1.x + f1.y));
    }
}

// ---------------------------------------------------------------------------
// Kernel 2: recurrence. 128 CTAs x 512 threads, 2 batch rows per CTA.
// Thread t: neuron n = t>>1, half kh = t&1 (k in [kh*128, kh*128+128)).
// W[n, half]: 40 k from SMEM (row t, pitch 44), 88 k in regs.
// h stored skewed (k + 4*(k>=128)) so kh=0/kh=1 lanes hit disjoint bank quads.
// Cross-half combine via shfl_xor(1). ONE barrier per step.
// ---------------------------------------------------------------------------
__global__ __launch_bounds__(512, 1) void rnn_kernel(
    const float* __restrict__ w_hh_f,
    const float* __restrict__ w_hh_b,
    float* __restrict__ out)
{
    extern __shared__ float sm[];
    float* Wsh = sm;                        // [512][WPITCH] = 22528 floats (90,112 B)
    float* hs  = sm + 512 * WPITCH;         // [2 buf][2 rows][HROW] = 1056 floats

    const int dir = blockIdx.x >> 6;
    const int jb  = blockIdx.x & 63;
    const int b0  = 2 * jb;
    const int t   = threadIdx.x;
    const int n   = t >> 1;
    const int kh  = t & 1;
    const int kbase = kh << 7;

    const float* __restrict__ W = dir ? w_hh_b : w_hh_f;

    // stage W: Wsh row r=t holds W[r>>1][(r&1)*128 + 0..K_SM_H)
    for (int idx = t; idx < 512 * K_SM_H; idx += 512) {
        int r = idx / K_SM_H;
        int k = idx - r * K_SM_H;
        Wsh[r * WPITCH + k] = W[(r >> 1) * H + (r & 1) * 128 + k];
    }
    // W[n, kbase+K_SM_H : kbase+128] -> 22 ulonglong2 (88 regs)
    ulonglong2 wreg[22];
    {
        const ulonglong2* wrow = reinterpret_cast<const ulonglong2*>(W + (size_t)n * H + kbase + K_SM_H);
        #pragma unroll
        for (int r = 0; r < 22; r++) wreg[r] = wrow[r];
    }
    // zero h buffers (incl. padding)
    for (int i = t; i < 4 * HROW; i += 512) hs[i] = 0.f;
    __syncthreads();

    // xp / out pointers (used by kh==0 lanes only)
    const float* xp0 = g_xp + ((size_t)dir * T * B + b0) * H + n;
    const float* xp1 = xp0 + H;
    const size_t step_stride = (size_t)B * H;
    float xa = 0.f, xb = 0.f;
    if (kh == 0) { xa = __ldg(xp0); xb = __ldg(xp1); }
    float* out_t = out + (size_t)dir * H + n;

    const ulonglong2* wv = reinterpret_cast<const ulonglong2*>(Wsh + t * WPITCH);
    const int khoff = kh ? 132 : 0;          // skewed read base for this half
    const int wroff = (n >= 128) ? (n + 4) : n;  // skewed write slot for h[n]

    int buf = 0;
    for (int s = 0; s < T; s++) {
        float nxa = 0.f, nxb = 0.f;
        if (kh == 0 && s < T - 1) {
            nxa = __ldg(xp0 + (size_t)(s + 1) * step_stride);
            nxb = __ldg(xp1 + (size_t)(s + 1) * step_stride);
        }

        const ulonglong2* hAv = reinterpret_cast<const ulonglong2*>(hs + buf * (2 * HROW) + khoff);
        const ulonglong2* hBv = reinterpret_cast<const ulonglong2*>(hs + buf * (2 * HROW) + HROW + khoff);

        unsigned long long aA0 = 0ull, aB0 = 0ull, aA1 = 0ull, aB1 = 0ull;

        // k in [kbase, kbase+40): W from shared
        #pragma unroll
        for (int i = 0; i < K_SM_H / 4; i++) {
            ulonglong2 w  = wv[i];
            ulonglong2 ha = hAv[i];
            ulonglong2 hb = hBv[i];
            aA0 = ffma2(w.x, ha.x, aA0);
            aB0 = ffma2(w.y, ha.y, aB0);
            aA1 = ffma2(w.x, hb.x, aA1);
            aB1 = ffma2(w.y, hb.y, aB1);
        }
        // k in [kbase+40, kbase+128): W from regs
        #pragma unroll
        for (int r = 0; r < 22; r++) {
            ulonglong2 w  = wreg[r];
            ulonglong2 ha = hAv[K_SM_H / 4 + r];
            ulonglong2 hb = hBv[K_SM_H / 4 + r];
            aA0 = ffma2(w.x, ha.x, aA0);
            aB0 = ffma2(w.y, ha.y, aB0);
            aA1 = ffma2(w.x, hb.x, aA1);
            aB1 = ffma2(w.y, hb.y, aB1);
        }

        float2 fA0 = u2f(aA0), fB0 = u2f(aB0);
        float2 fA1 = u2f(aA1), fB1 = u2f(aB1);
        float s0 = (fA0.x + fA0.y) + (fB0.x + fB0.y);
        float s1 = (fA1.x + fA1.y) + (fB1.x + fB1.y);

        // cross-half combine within lane pair
        s0 += __shfl_xor_sync(0xFFFFFFFFu, s0, 1);
        s1 += __shfl_xor_sync(0xFFFFFFFFu, s1, 1);

        const int nb = buf ^ 1;
        if (kh == 0) {
            float h0 = fmaxf(xa + s0, 0.f);
            float h1 = fmaxf(xb + s1, 0.f);

            const int time = dir ? (T - 1 - s) : s;
            out_t[((size_t)b0 * T + time) * (2 * H)] = h0;
            out_t[((size_t)(b0 + 1) * T + time) * (2 * H)] = h1;

            float* hw = hs + nb * (2 * HROW) + wroff;
            hw[0]    = h0;
            hw[HROW] = h1;
            xa = nxa;
            xb = nxb;
        }
        __syncthreads();
        buf = nb;
    }
}

// ---------------------------------------------------------------------------
extern "C" void kernel_launch(void* const* d_in, const int* in_sizes, int n_in,
                              void* d_out, int out_size)
{
    const float* x      = (const float*)d_in[0];
    const float* w_ih_f = (const float*)d_in[1];
    const float* w_hh_f = (const float*)d_in[2];
    const float* b_ih_f = (const float*)d_in[3];
    const float* b_hh_f = (const float*)d_in[4];
    const float* w_ih_b = (const float*)d_in[5];
    const float* w_hh_b = (const float*)d_in[6];
    const float* b_ih_b = (const float*)d_in[7];
    const float* b_hh_b = (const float*)d_in[8];
    float* out = (float*)d_out;

    const int smem_bytes = (512 * WPITCH + 4 * HROW) * 4;   // 90112 + 4224 = 94336 B
    static bool attr_set = false;
    if (!attr_set) {
        cudaFuncSetAttribute(rnn_kernel, cudaFuncAttributeMaxDynamicSharedMemorySize, smem_bytes);
        attr_set = true;
    }

    proj_kernel<<<dim3(T, 2), 256>>>(x, w_ih_f, b_ih_f, b_hh_f, w_ih_b, b_ih_b, b_hh_b);
    rnn_kernel<<<128, 512, smem_bytes>>>(w_hh_f, w_hh_b, out);
}

// round 5
// speedup vs baseline: 1.1330x; 1.0254x over previous
#include <cuda_runtime.h>
#include <cstdint>

// Problem constants
#define B 128
#define T 512
#define I 50
#define H 256

// recurrence config: 512 threads, thread t -> (neuron pair nb = t>>2, k-quarter ks = t&3)
// Each thread: 2 rows x 2 neurons x 64 k. Cross-ks combine via warp reduce-scatter.
#define KREG   40           // k per neuron from registers (20 ull = 40 regs/neuron)
#define KSM    24           // k per neuron from shared memory
#define WPITCH 52           // smem pitch (floats) per thread row of 48 W floats; 20t mod 32 conflict-free
#define HROW   304          // padded h row; skew h[k] -> k + 8*(k>>6); 304 mod 32 = 16 separates rows
#define HBUF   (2 * HROW)   // two batch rows per buffer

// Scratch: xp[dir][t][b][h]  (fp32), 134 MB
__device__ float g_xp[2u * T * B * H];

// ---------------------------------------------------------------------------
// packed fp32x2 helpers (Blackwell)
// ---------------------------------------------------------------------------
__device__ __forceinline__ unsigned long long ffma2(unsigned long long a,
                                                    unsigned long long b,
                                                    unsigned long long c) {
    unsigned long long d;
    asm("fma.rn.f32x2 %0, %1, %2, %3;" : "=l"(d) : "l"(a), "l"(b), "l"(c));
    return d;
}
__device__ __forceinline__ float2 u2f(unsigned long long v) {
    float2 f;
    asm("mov.b64 {%0, %1}, %2;" : "=f"(f.x), "=f"(f.y) : "l"(v));
    return f;
}
__device__ __forceinline__ unsigned long long f2u(float lo, float hi) {
    unsigned long long v;
    asm("mov.b64 %0, {%1, %2};" : "=l"(v) : "f"(lo), "f"(hi));
    return v;
}

// ---------------------------------------------------------------------------
// Kernel 1: input projection (unchanged — ~115 us, not the bottleneck)
// ---------------------------------------------------------------------------
#define IPAD 52
__global__ __launch_bounds__(256) void proj_kernel(
    const float* __restrict__ x,
    const float* __restrict__ w_ih_f, const float* __restrict__ b_ih_f, const float* __restrict__ b_hh_f,
    const float* __restrict__ w_ih_b, const float* __restrict__ b_ih_b, const float* __restrict__ b_hh_b)
{
    __shared__ float xs[B * IPAD];

    const int t   = blockIdx.x;
    const int dir = blockIdx.y;
    const int h   = threadIdx.x;
    const int t_src = dir ? (T - 1 - t) : t;

    for (int idx = threadIdx.x; idx < B * IPAD; idx += blockDim.x) xs[idx] = 0.f;
    __syncthreads();
    for (int idx = threadIdx.x; idx < B * I; idx += blockDim.x) {
        int b = idx / I;
        int i = idx - b * I;
        xs[b * IPAD + i] = x[((size_t)b * T + t_src) * I + i];
    }

    const float* w = dir ? w_ih_b : w_ih_f;
    unsigned long long wr[26];
    {
        const float* wp = w + (size_t)h * I;
        #pragma unroll
        for (int i = 0; i < 25; i++) wr[i] = f2u(wp[2 * i], wp[2 * i + 1]);
        wr[25] = 0ull;
    }
    const float bias = dir ? (b_ih_b[h] + b_hh_b[h]) : (b_ih_f[h] + b_hh_f[h]);

    __syncthreads();

    float* xp_out = g_xp + (((size_t)dir * T + t) * B) * H + h;
    #pragma unroll 2
    for (int b = 0; b < B; b++) {
        const ulonglong2* xb = reinterpret_cast<const ulonglong2*>(&xs[b * IPAD]);
        unsigned long long a0 = 0ull, a1 = 0ull;
        #pragma unroll
        for (int i = 0; i < 13; i++) {
            ulonglong2 xv = xb[i];
            a0 = ffma2(xv.x, wr[2 * i], a0);
            a1 = ffma2(xv.y, wr[2 * i + 1], a1);
        }
        float2 f0 = u2f(a0), f1 = u2f(a1);
        xp_out[(size_t)b * H] = bias + ((f0.x + f0.y) + (f1.x + f1.y));
    }
}

// ---------------------------------------------------------------------------
// Kernel 2: recurrence. 128 CTAs x 512 threads, 2 batch rows per CTA.
// Thread t: nb = t>>2 -> neurons {2nb, 2nb+1}; ks = t&3 -> k in [64ks, 64ks+64).
// Each thread computes 4 partial dots (2 rows x 2 neurons) over its 64 k.
// h stored skewed (k + 8*(k>>6)) so the 4 k-quarters hit disjoint bank quads.
// W: 40 k/neuron in regs, 24 k/neuron from smem (pitch 52, conflict-free).
// Combine over ks via 2-stage warp reduce-scatter (3 shuffles); each thread
// then owns exactly one output (row = ks>>1, neuron = 2nb + (ks&1)).
// ONE __syncthreads per step.
// ---------------------------------------------------------------------------
__global__ __launch_bounds__(512, 1) void rnn_kernel(
    const float* __restrict__ w_hh_f,
    const float* __restrict__ w_hh_b,
    float* __restrict__ out)
{
    extern __shared__ float sm[];
    float* Wsh = sm;                        // [512][WPITCH] = 26624 floats (106,496 B)
    float* hs  = sm + 512 * WPITCH;         // [2 buf][2 rows][HROW] = 1216 floats

    const int dir = blockIdx.x >> 6;
    const int jb  = blockIdx.x & 63;
    const int b0  = 2 * jb;
    const int t   = threadIdx.x;
    const int nb  = t >> 2;
    const int ks  = t & 3;

    const float* __restrict__ W = dir ? w_hh_b : w_hh_f;

    // stage W smem part: row tt holds [n0: k'=KREG..KREG+23][n1: same], k-base 64*(tt&3)
    for (int idx = t; idx < 512 * 48; idx += 512) {
        int tt  = idx / 48;
        int rem = idx - tt * 48;
        int j   = (rem >= 24) ? 1 : 0;
        int kk  = rem - 24 * j;
        Wsh[tt * WPITCH + rem] = W[(size_t)(2 * (tt >> 2) + j) * H + 64 * (tt & 3) + KREG + kk];
    }
    // W reg part: 40 floats per neuron = 20 packed pairs
    unsigned long long w0[20], w1[20];
    {
        const ulonglong2* p0 = reinterpret_cast<const ulonglong2*>(W + (size_t)(2 * nb) * H + 64 * ks);
        const ulonglong2* p1 = reinterpret_cast<const ulonglong2*>(W + (size_t)(2 * nb + 1) * H + 64 * ks);
        #pragma unroll
        for (int r = 0; r < 10; r++) {
            ulonglong2 v0 = p0[r]; w0[2 * r] = v0.x; w0[2 * r + 1] = v0.y;
            ulonglong2 v1 = p1[r]; w1[2 * r] = v1.x; w1[2 * r + 1] = v1.y;
        }
    }
    // zero h buffers (incl. skew padding)
    for (int i = t; i < 2 * HBUF; i += 512) hs[512 * WPITCH - 512 * WPITCH + i] = 0.f;  // hs[i]
    __syncthreads();

    const int row = ks >> 1;               // batch row this thread outputs
    const int nn  = 2 * nb + (ks & 1);     // neuron this thread outputs
    const int hoff = 72 * ks;              // skewed read base of this thread's k-block
    const int wpos = nn + 8 * (nn >> 6);   // skewed write slot for h[nn]

    const float* xp = g_xp + ((size_t)dir * T * B + (b0 + row)) * H + nn;
    const size_t step_stride = (size_t)B * H;
    float xv = __ldg(xp);
    float* outp = out + (size_t)dir * H + nn;

    const ulonglong2* wsm = reinterpret_cast<const ulonglong2*>(Wsh + t * WPITCH);

    int buf = 0;
    for (int s = 0; s < T; s++) {
        float nx = 0.f;
        if (s < T - 1) nx = __ldg(xp + (size_t)(s + 1) * step_stride);

        const ulonglong2* hA = reinterpret_cast<const ulonglong2*>(hs + buf * HBUF + hoff);
        const ulonglong2* hB = reinterpret_cast<const ulonglong2*>(hs + buf * HBUF + HROW + hoff);

        unsigned long long a00 = 0ull, a01 = 0ull, a10 = 0ull, a11 = 0ull;

        // k' in [0, 40): W from regs
        #pragma unroll
        for (int i = 0; i < 10; i++) {
            ulonglong2 ha = hA[i];
            ulonglong2 hb = hB[i];
            a00 = ffma2(w0[2 * i],     ha.x, a00);
            a00 = ffma2(w0[2 * i + 1], ha.y, a00);
            a01 = ffma2(w1[2 * i],     ha.x, a01);
            a01 = ffma2(w1[2 * i + 1], ha.y, a01);
            a10 = ffma2(w0[2 * i],     hb.x, a10);
            a10 = ffma2(w0[2 * i + 1], hb.y, a10);
            a11 = ffma2(w1[2 * i],     hb.x, a11);
            a11 = ffma2(w1[2 * i + 1], hb.y, a11);
        }
        // k' in [40, 64): W from smem
        #pragma unroll
        for (int i = 0; i < 6; i++) {
            ulonglong2 wa = wsm[i];
            ulonglong2 wb = wsm[6 + i];
            ulonglong2 ha = hA[10 + i];
            ulonglong2 hb = hB[10 + i];
            a00 = ffma2(wa.x, ha.x, a00);
            a00 = ffma2(wa.y, ha.y, a00);
            a01 = ffma2(wb.x, ha.x, a01);
            a01 = ffma2(wb.y, ha.y, a01);
            a10 = ffma2(wa.x, hb.x, a10);
            a10 = ffma2(wa.y, hb.y, a10);
            a11 = ffma2(wb.x, hb.x, a11);
            a11 = ffma2(wb.y, hb.y, a11);
        }

        float2 f00 = u2f(a00), f01 = u2f(a01), f10 = u2f(a10), f11 = u2f(a11);
        float p0 = f00.x + f00.y;   // (row0, n0) partial
        float p1 = f01.x + f01.y;   // (row0, n1)
        float p2 = f10.x + f10.y;   // (row1, n0)
        float p3 = f11.x + f11.y;   // (row1, n1)

        // reduce-scatter over ks (4 k-quarters): lane ks ends with (row=ks>>1, n-bit=ks&1)
        float r1a = __shfl_xor_sync(0xFFFFFFFFu, (ks & 1) ? p0 : p1, 1);
        float r1b = __shfl_xor_sync(0xFFFFFFFFu, (ks & 1) ? p2 : p3, 1);
        float c0 = ((ks & 1) ? p1 : p0) + r1a;   // row0, own n-bit
        float c1 = ((ks & 1) ? p3 : p2) + r1b;   // row1, own n-bit
        float r2 = __shfl_xor_sync(0xFFFFFFFFu, (ks & 2) ? c0 : c1, 2);
        float v  = ((ks & 2) ? c1 : c0) + r2;    // full dot for (row, nn)

        float hnew = fmaxf(xv + v, 0.f);

        const int time = dir ? (T - 1 - s) : s;
        outp[((size_t)(b0 + row) * T + time) * (2 * H)] = hnew;

        const int nbf = buf ^ 1;
        hs[nbf * HBUF + row * HROW + wpos] = hnew;
        __syncthreads();

        buf = nbf;
        xv = nx;
    }
}

// ---------------------------------------------------------------------------
extern "C" void kernel_launch(void* const* d_in, const int* in_sizes, int n_in,
                              void* d_out, int out_size)
{
    const float* x      = (const float*)d_in[0];
    const float* w_ih_f = (const float*)d_in[1];
    const float* w_hh_f = (const float*)d_in[2];
    const float* b_ih_f = (const float*)d_in[3];
    const float* b_hh_f = (const float*)d_in[4];
    const float* w_ih_b = (const float*)d_in[5];
    const float* w_hh_b = (const float*)d_in[6];
    const float* b_ih_b = (const float*)d_in[7];
    const float* b_hh_b = (const float*)d_in[8];
    float* out = (float*)d_out;

    const int smem_bytes = (512 * WPITCH + 2 * HBUF) * 4;   // 106496 + 4864 = 111360 B
    static bool attr_set = false;
    if (!attr_set) {
        cudaFuncSetAttribute(rnn_kernel, cudaFuncAttributeMaxDynamicSharedMemorySize, smem_bytes);
        attr_set = true;
    }

    proj_kernel<<<dim3(T, 2), 256>>>(x, w_ih_f, b_ih_f, b_hh_f, w_ih_b, b_ih_b, b_hh_b);
    rnn_kernel<<<128, 512, smem_bytes>>>(w_hh_f, w_hh_b, out);
}